// round 14
// baseline (speedup 1.0000x reference)
#include <cuda_runtime.h>
#include <cuda_bf16.h>
#include <math.h>
#include <stdint.h>

// Problem constants
#define CC    128
#define HWSZ  262144      // 512*512
#define BK    512         // B*K
#define NNEG  7
#define PP    4096
#define TAUI  (1.0f/0.07f)

// MMA tiling
#define QTILE 128
#define PTILE 128
#define NPT   (PP/PTILE)  // 32 proto tiles
#define NBLK  ((BK/QTILE)*(PP/PTILE))   // 128 blocks (all resident: 1/SM)

// smem layout: 4 tiles of 128 rows x 272 B (256 data + 16 pad)
#define STRB    272
#define TILE_B  (128*STRB)    // 34816
#define AH_OFF  0
#define AL_OFF  (TILE_B)
#define BH_OFF  (2*TILE_B)
#define BL_OFF  (3*TILE_B)
#define RN_OFF  (4*TILE_B)    // 139264
#define SMEM_MMA (RN_OFF + 512)

// Scratch (device globals — no allocation allowed)
__device__ __align__(256) float         g_qn[BK*CC];
__device__ __align__(256) float         g_rnorm[PP];
__device__ __align__(256) float         g_pmax[BK*NPT];
__device__ __align__(256) float         g_nlog[BK*NNEG];
__device__ __align__(256) __nv_bfloat16 g_qh[BK*CC];
__device__ __align__(256) __nv_bfloat16 g_ql[BK*CC];
__device__ __align__(256) __nv_bfloat16 g_ph[PP*CC];
__device__ __align__(256) __nv_bfloat16 g_pl[PP*CC];
__device__ unsigned int g_c0 = 0;   // barrier 1 (all blocks) — monotonic
__device__ unsigned int g_c1 = 0;   // barrier 2 (blocks 0,1 wait) — monotonic

__device__ __forceinline__ uint32_t smem_u32(const void* p) {
    uint32_t a;
    asm("{ .reg .u64 t; cvta.to.shared.u64 t, %1; cvt.u32.u64 %0, t; }"
        : "=r"(a) : "l"(p));
    return a;
}

#define LDSM4(r0, r1, r2, r3, addr) \
    asm volatile("ldmatrix.sync.aligned.m8n8.x4.shared.b16 {%0,%1,%2,%3}, [%4];" \
        : "=r"(r0), "=r"(r1), "=r"(r2), "=r"(r3) : "r"(addr))

#define MMA16816(c, a0, a1, a2, a3, b0, b1) \
    asm volatile("mma.sync.aligned.m16n8k16.row.col.f32.bf16.bf16.f32 " \
        "{%0,%1,%2,%3}, {%4,%5,%6,%7}, {%8,%9}, {%0,%1,%2,%3};" \
        : "+f"((c)[0]), "+f"((c)[1]), "+f"((c)[2]), "+f"((c)[3]) \
        : "r"(a0), "r"(a1), "r"(a2), "r"(a3), "r"(b0), "r"(b1))

__device__ __forceinline__ void split_store(float v, __nv_bfloat16* hi, __nv_bfloat16* lo) {
    __nv_bfloat16 h = __float2bfloat16(v);
    *hi = h;
    *lo = __float2bfloat16(v - __bfloat162float(h));
}

// ---------------------------------------------------------------------------
// Single persistent kernel.  grid=(4,32), block=256, 1 block/SM (all resident)
//   Phase 0: distributed prep — 4 queries + 32 pool rows per block (uniform).
//   Barrier 1 (all 128 blocks).
//   Phase 1: split-bf16 mma.sync tile + row max + negative logits.
//   Barrier 2: blocks 0,1 wait, then softmax CE + mean -> out.
// ---------------------------------------------------------------------------
__global__ void __launch_bounds__(256, 1)
k_all(const float* __restrict__ qf,
      const float* __restrict__ pool,
      const int*   __restrict__ qidx,
      const float* __restrict__ neg,
      float* __restrict__ out) {
    extern __shared__ __align__(128) uint8_t smem[];
    __shared__ float qss[8];
    __shared__ unsigned int s_tgt;
    __shared__ float sred[8];

    int t    = threadIdx.x;
    int lane = t & 31;
    int wid  = t >> 5;
    int flat  = blockIdx.y * 4 + blockIdx.x;
    int qbase = blockIdx.x * QTILE;
    int pbase = blockIdx.y * PTILE;

    if (flat == 0 && t == 0) out[0] = 0.0f;

    // ================= Phase 0: distributed prep =================
    // queries: 4 per block (64 threads each, 2 channels per thread)
    {
        int qq = t >> 6;                 // 0..3
        int q  = flat * 4 + qq;
        int c0 = t & 63;
        int b  = q >> 6;
        int idx = qidx[q];
        const float* src = qf + ((size_t)(b * CC + c0)) * HWSZ + (size_t)idx;
        float v0 = src[0];
        float v1 = src[(size_t)64 * HWSZ];
        float ss = v0 * v0 + v1 * v1;
        #pragma unroll
        for (int o = 16; o; o >>= 1) ss += __shfl_xor_sync(0xffffffffu, ss, o);
        if (lane == 0) qss[wid] = ss;
        __syncthreads();
        float tot = qss[2 * qq] + qss[2 * qq + 1];
        float inv = 1.0f / fmaxf(sqrtf(tot), 1e-12f);
        float n0 = v0 * inv, n1 = v1 * inv;
        g_qn[q * CC + c0]      = n0;
        g_qn[q * CC + c0 + 64] = n1;
        split_store(n0, &g_qh[q * CC + c0],      &g_ql[q * CC + c0]);
        split_store(n1, &g_qh[q * CC + c0 + 64], &g_ql[q * CC + c0 + 64]);
    }

    // pool: 32 rows per block (8 threads per row, 16 channels per thread)
    {
        int row = flat * 32 + (t >> 3);
        int ch0 = (t & 7) * 16;
        const float4* src = (const float4*)(pool + (size_t)row * CC + ch0);
        float4 v[4];
        float ss = 0.0f;
        #pragma unroll
        for (int i = 0; i < 4; i++) {
            v[i] = src[i];
            ss += v[i].x*v[i].x + v[i].y*v[i].y + v[i].z*v[i].z + v[i].w*v[i].w;
        }
        #pragma unroll
        for (int o = 4; o; o >>= 1) ss += __shfl_xor_sync(0xffffffffu, ss, o);
        if ((t & 7) == 0) g_rnorm[row] = 1.0f / fmaxf(sqrtf(ss), 1e-12f);

        uint32_t hp[8], lp[8];
        #pragma unroll
        for (int i = 0; i < 4; i++) {
            float vv[4] = {v[i].x, v[i].y, v[i].z, v[i].w};
            #pragma unroll
            for (int j = 0; j < 2; j++) {
                __nv_bfloat16 h0 = __float2bfloat16(vv[2*j]);
                __nv_bfloat16 h1 = __float2bfloat16(vv[2*j+1]);
                __nv_bfloat16 l0 = __float2bfloat16(vv[2*j]   - __bfloat162float(h0));
                __nv_bfloat16 l1 = __float2bfloat16(vv[2*j+1] - __bfloat162float(h1));
                hp[i*2+j] = (uint32_t)__bfloat16_as_ushort(h0)
                          | ((uint32_t)__bfloat16_as_ushort(h1) << 16);
                lp[i*2+j] = (uint32_t)__bfloat16_as_ushort(l0)
                          | ((uint32_t)__bfloat16_as_ushort(l1) << 16);
            }
        }
        uint4* dh = (uint4*)((char*)g_ph + ((size_t)row * CC + ch0) * 2);
        uint4* dl = (uint4*)((char*)g_pl + ((size_t)row * CC + ch0) * 2);
        dh[0] = make_uint4(hp[0], hp[1], hp[2], hp[3]);
        dh[1] = make_uint4(hp[4], hp[5], hp[6], hp[7]);
        dl[0] = make_uint4(lp[0], lp[1], lp[2], lp[3]);
        dl[1] = make_uint4(lp[4], lp[5], lp[6], lp[7]);
    }

    // ---- Barrier 1: all 128 blocks (all resident -> deadlock-free) ----
    __threadfence();
    __syncthreads();
    if (t == 0) {
        unsigned int old = atomicAdd(&g_c0, 1u);
        s_tgt = ((old >> 7) << 7) + (unsigned int)NBLK;
    }
    __syncthreads();
    if (t == 0) {
        while (*((volatile unsigned int*)&g_c0) < s_tgt) { }
    }
    __syncthreads();
    __threadfence();   // acquire all g_* prep outputs

    // ================= Phase 1: MMA tile =================
    {
        int row = t >> 1, half = t & 1;
        const uint4* sah = (const uint4*)((const char*)(g_qh + (size_t)(qbase + row) * CC) + half * 128);
        const uint4* sal = (const uint4*)((const char*)(g_ql + (size_t)(qbase + row) * CC) + half * 128);
        const uint4* sbh = (const uint4*)((const char*)(g_ph + (size_t)(pbase + row) * CC) + half * 128);
        const uint4* sbl = (const uint4*)((const char*)(g_pl + (size_t)(pbase + row) * CC) + half * 128);
        uint4* dah = (uint4*)(smem + AH_OFF + row * STRB + half * 128);
        uint4* dal = (uint4*)(smem + AL_OFF + row * STRB + half * 128);
        uint4* dbh = (uint4*)(smem + BH_OFF + row * STRB + half * 128);
        uint4* dbl = (uint4*)(smem + BL_OFF + row * STRB + half * 128);
        #pragma unroll
        for (int i = 0; i < 8; i++) {
            dah[i] = sah[i]; dal[i] = sal[i];
            dbh[i] = sbh[i]; dbl[i] = sbl[i];
        }
        if (t < 128) ((float*)(smem + RN_OFF))[t] = g_rnorm[pbase + t];
    }
    __syncthreads();

    uint32_t sb = smem_u32(smem);
    int m0 = wid * 16;
    uint32_t aoff = (uint32_t)((m0 + (lane & 15)) * STRB + ((lane & 16) ? 16 : 0));
    uint32_t boff = (uint32_t)(((lane & 7) + ((lane & 16) ? 8 : 0)) * STRB + ((lane & 8) ? 16 : 0));
    uint32_t aAh = sb + AH_OFF + aoff;
    uint32_t aAl = sb + AL_OFF + aoff;
    uint32_t bBh = sb + BH_OFF + boff;
    uint32_t bBl = sb + BL_OFF + boff;

    float acc[16][4];
    #pragma unroll
    for (int i = 0; i < 16; i++)
        #pragma unroll
        for (int j = 0; j < 4; j++) acc[i][j] = 0.0f;

    for (int ks = 0; ks < 8; ks++) {
        uint32_t kb = ks * 32;
        uint32_t ah0, ah1, ah2, ah3, al0, al1, al2, al3;
        LDSM4(ah0, ah1, ah2, ah3, aAh + kb);
        LDSM4(al0, al1, al2, al3, aAl + kb);
        #pragma unroll
        for (int j = 0; j < 8; j++) {
            uint32_t bh0, bh1, bh2, bh3, bl0, bl1, bl2, bl3;
            LDSM4(bh0, bh1, bh2, bh3, bBh + j * 16 * STRB + kb);
            LDSM4(bl0, bl1, bl2, bl3, bBl + j * 16 * STRB + kb);
            MMA16816(acc[2*j],   ah0, ah1, ah2, ah3, bh0, bh1);
            MMA16816(acc[2*j],   ah0, ah1, ah2, ah3, bl0, bl1);
            MMA16816(acc[2*j],   al0, al1, al2, al3, bh0, bh1);
            MMA16816(acc[2*j+1], ah0, ah1, ah2, ah3, bh2, bh3);
            MMA16816(acc[2*j+1], ah0, ah1, ah2, ah3, bl2, bl3);
            MMA16816(acc[2*j+1], al0, al1, al2, al3, bh2, bh3);
        }
    }

    // sim = acc * rnorm, max over all 128 protos -> g_pmax
    {
        const float* rn = (const float*)(smem + RN_OFF);
        float mx1 = -3e38f, mx2 = -3e38f;
        #pragma unroll
        for (int nb = 0; nb < 16; nb++) {
            int n = nb * 8 + 2 * (lane & 3);
            float r0 = rn[n], r1 = rn[n + 1];
            mx1 = fmaxf(mx1, fmaxf(acc[nb][0] * r0, acc[nb][1] * r1));
            mx2 = fmaxf(mx2, fmaxf(acc[nb][2] * r0, acc[nb][3] * r1));
        }
        #pragma unroll
        for (int o = 1; o <= 2; o <<= 1) {
            mx1 = fmaxf(mx1, __shfl_xor_sync(0xffffffffu, mx1, o));
            mx2 = fmaxf(mx2, __shfl_xor_sync(0xffffffffu, mx2, o));
        }
        if ((lane & 3) == 0) {
            int q1 = qbase + m0 + (lane >> 2);
            g_pmax[q1 * NPT + blockIdx.y]       = mx1;
            g_pmax[(q1 + 8) * NPT + blockIdx.y] = mx2;
        }
    }

    // negative logits: 4 queries per block, 28 warp-dots
    #pragma unroll
    for (int i = 0; i < 4; i++) {
        int pair = wid * 4 + i;
        if (pair < 28) {
            int q = flat * 4 + pair / NNEG;
            int n = pair % NNEG;
            float4 qv = *(const float4*)(g_qn + (size_t)q * CC + lane * 4);
            float4 nv = *(const float4*)(neg + ((size_t)q * NNEG + n) * CC + lane * 4);
            float dp = qv.x*nv.x + qv.y*nv.y + qv.z*nv.z + qv.w*nv.w;
            float ss = nv.x*nv.x + nv.y*nv.y + nv.z*nv.z + nv.w*nv.w;
            #pragma unroll
            for (int o = 16; o; o >>= 1) {
                dp += __shfl_xor_sync(0xffffffffu, dp, o);
                ss += __shfl_xor_sync(0xffffffffu, ss, o);
            }
            if (lane == 0)
                g_nlog[q * NNEG + n] = dp / fmaxf(sqrtf(ss), 1e-12f) * TAUI;
        }
    }

    // ---- Barrier 2: publish; only blocks 0,1 wait ----
    __threadfence();
    __syncthreads();
    if (t == 0) {
        unsigned int old = atomicAdd(&g_c1, 1u);
        s_tgt = ((old >> 7) << 7) + (unsigned int)NBLK;
    }
    __syncthreads();
    if (flat >= 2) return;
    if (t == 0) {
        while (*((volatile unsigned int*)&g_c1) < s_tgt) { }
    }
    __syncthreads();
    __threadfence();   // acquire g_pmax / g_nlog

    // ---- final: thread-per-query softmax CE, block reduce, atomicAdd ----
    {
        int q = flat * 256 + t;
        float mx = -3e38f;
        #pragma unroll
        for (int j = 0; j < NPT; j++) mx = fmaxf(mx, g_pmax[q * NPT + j]);
        float l0 = mx * TAUI;

        float ln[NNEG];
        #pragma unroll
        for (int n = 0; n < NNEG; n++) ln[n] = g_nlog[q * NNEG + n];

        float m = l0;
        #pragma unroll
        for (int n = 0; n < NNEG; n++) m = fmaxf(m, ln[n]);
        float se = expf(l0 - m);
        #pragma unroll
        for (int n = 0; n < NNEG; n++) se += expf(ln[n] - m);
        float loss = logf(se) + m - l0;      // = -(log_softmax[0])

        #pragma unroll
        for (int o = 16; o; o >>= 1) loss += __shfl_xor_sync(0xffffffffu, loss, o);
        if (lane == 0) sred[wid] = loss;
        __syncthreads();
        if (t == 0) {
            float s = 0.0f;
            #pragma unroll
            for (int i = 0; i < 8; i++) s += sred[i];
            atomicAdd(out, s * (1.0f / (float)BK));
        }
    }
}

// ---------------------------------------------------------------------------
extern "C" void kernel_launch(void* const* d_in, const int* in_sizes, int n_in,
                              void* d_out, int out_size) {
    const float* qf   = (const float*)d_in[0];  // [8,128,512,512]
    const float* pool = (const float*)d_in[1];  // [4096,128]
    const float* neg  = (const float*)d_in[2];  // [8,64,7,128]
    const int*   qidx = (const int*)d_in[3];    // [8,64]
    float* out = (float*)d_out;

    cudaFuncSetAttribute(k_all, cudaFuncAttributeMaxDynamicSharedMemorySize, SMEM_MMA);

    k_all<<<dim3(BK / QTILE, PP / PTILE), 256, SMEM_MMA>>>(qf, pool, qidx, neg, out);
}

// round 15
// speedup vs baseline: 1.0900x; 1.0900x over previous
#include <cuda_runtime.h>
#include <cuda_bf16.h>
#include <math.h>
#include <stdint.h>

// Problem constants
#define CC    128
#define HWSZ  262144      // 512*512
#define BK    512         // B*K
#define NNEG  7
#define PP    4096
#define TAUI  (1.0f/0.07f)

// MMA tiling
#define QTILE 128
#define PTILE 128
#define NPT   (PP/PTILE)  // 32 proto tiles
#define NBLK  ((BK/QTILE)*(PP/PTILE))   // 128 blocks (all resident: 1/SM)

// smem layout for k_mma: 4 tiles of 128 rows x 272 B (256 data + 16 pad)
#define STRB    272
#define TILE_B  (128*STRB)    // 34816
#define AH_OFF  0
#define AL_OFF  (TILE_B)
#define BH_OFF  (2*TILE_B)
#define BL_OFF  (3*TILE_B)
#define RN_OFF  (4*TILE_B)    // 139264
#define SMEM_MMA (RN_OFF + 512)

// Scratch (device globals — no allocation allowed)
__device__ __align__(256) float         g_rnorm[PP];
__device__ __align__(256) float         g_pmax[BK*NPT];
__device__ __align__(256) float         g_nlog[BK*NNEG];
__device__ __align__(256) __nv_bfloat16 g_qh[BK*CC];
__device__ __align__(256) __nv_bfloat16 g_ql[BK*CC];
__device__ __align__(256) __nv_bfloat16 g_ph[PP*CC];
__device__ __align__(256) __nv_bfloat16 g_pl[PP*CC];
__device__ unsigned int g_cnt = 0;   // monotonic barrier counter (mma tail)

__device__ __forceinline__ uint32_t smem_u32(const void* p) {
    uint32_t a;
    asm("{ .reg .u64 t; cvta.to.shared.u64 t, %1; cvt.u32.u64 %0, t; }"
        : "=r"(a) : "l"(p));
    return a;
}

#define LDSM4(r0, r1, r2, r3, addr) \
    asm volatile("ldmatrix.sync.aligned.m8n8.x4.shared.b16 {%0,%1,%2,%3}, [%4];" \
        : "=r"(r0), "=r"(r1), "=r"(r2), "=r"(r3) : "r"(addr))

#define MMA16816(c, a0, a1, a2, a3, b0, b1) \
    asm volatile("mma.sync.aligned.m16n8k16.row.col.f32.bf16.bf16.f32 " \
        "{%0,%1,%2,%3}, {%4,%5,%6,%7}, {%8,%9}, {%0,%1,%2,%3};" \
        : "+f"((c)[0]), "+f"((c)[1]), "+f"((c)[2]), "+f"((c)[3]) \
        : "r"(a0), "r"(a1), "r"(a2), "r"(a3), "r"(b0), "r"(b1))

// ---------------------------------------------------------------------------
// Kernel 1: prep.  grid=768, block=256
//   blocks [0,512): pool rows (8/block, warp per row): rnorm + bf16 hi/lo split
//   blocks [512,768): queries (2/block, 128 thr each): gather, normalize,
//       bf16 split, AND the 7 negative logits for each query -> g_nlog.
// ---------------------------------------------------------------------------
__global__ void k_prep(const float* __restrict__ pool,
                       const float* __restrict__ qf,
                       const int*   __restrict__ qidx,
                       const float* __restrict__ neg,
                       float* __restrict__ out) {
    int bid = blockIdx.x;
    int t   = threadIdx.x;
    if (bid == 0 && t == 0) out[0] = 0.0f;

    if (bid < 512) {
        int p    = bid * 8 + (t >> 5);
        int lane = t & 31;
        float4 v = *(const float4*)(pool + (size_t)p * CC + lane * 4);
        float ss = v.x*v.x + v.y*v.y + v.z*v.z + v.w*v.w;
        #pragma unroll
        for (int o = 16; o; o >>= 1) ss += __shfl_xor_sync(0xffffffffu, ss, o);
        if (lane == 0) g_rnorm[p] = 1.0f / fmaxf(sqrtf(ss), 1e-12f);

        float vv[4] = {v.x, v.y, v.z, v.w};
        uint32_t hp[2], lp[2];
        #pragma unroll
        for (int i = 0; i < 2; i++) {
            __nv_bfloat16 h0 = __float2bfloat16(vv[2*i]);
            __nv_bfloat16 h1 = __float2bfloat16(vv[2*i+1]);
            __nv_bfloat16 l0 = __float2bfloat16(vv[2*i]   - __bfloat162float(h0));
            __nv_bfloat16 l1 = __float2bfloat16(vv[2*i+1] - __bfloat162float(h1));
            hp[i] = (uint32_t)__bfloat16_as_ushort(h0)
                  | ((uint32_t)__bfloat16_as_ushort(h1) << 16);
            lp[i] = (uint32_t)__bfloat16_as_ushort(l0)
                  | ((uint32_t)__bfloat16_as_ushort(l1) << 16);
        }
        *(uint2*)((char*)g_ph + ((size_t)p * CC + lane * 4) * 2) = make_uint2(hp[0], hp[1]);
        *(uint2*)((char*)g_pl + ((size_t)p * CC + lane * 4) * 2) = make_uint2(lp[0], lp[1]);
    } else {
        __shared__ float sred[8];
        __shared__ float sdp[2][4][NNEG];
        __shared__ float sss[2][4][NNEG];
        int grp  = t >> 7;                       // 0 or 1
        int q    = (bid - 512) * 2 + grp;
        int c    = t & 127;
        int wloc = (t >> 5) & 3;                 // warp within grp
        int lane = t & 31;
        int b    = q >> 6;
        int idx  = qidx[q];

        float v = qf[((size_t)(b * CC + c)) * HWSZ + (size_t)idx];

        // issue the 7 negative loads early (independent of the norm)
        float nx[NNEG];
        const float* nb = neg + ((size_t)q * NNEG) * CC + c;
        #pragma unroll
        for (int n = 0; n < NNEG; n++) nx[n] = nb[(size_t)n * CC];

        float ss = v * v;
        #pragma unroll
        for (int o = 16; o; o >>= 1) ss += __shfl_xor_sync(0xffffffffu, ss, o);
        if ((t & 31) == 0) sred[t >> 5] = ss;
        __syncthreads();
        float tot = sred[grp*4+0] + sred[grp*4+1] + sred[grp*4+2] + sred[grp*4+3];
        float inv = 1.0f / fmaxf(sqrtf(tot), 1e-12f);
        float nv = v * inv;
        __nv_bfloat16 h = __float2bfloat16(nv);
        g_qh[q * CC + c] = h;
        g_ql[q * CC + c] = __float2bfloat16(nv - __bfloat162float(h));

        // negative logits: dp = <q_norm, neg>, ss = |neg|^2, per neg
        #pragma unroll
        for (int n = 0; n < NNEG; n++) {
            float d = nv * nx[n];
            float s = nx[n] * nx[n];
            #pragma unroll
            for (int o = 16; o; o >>= 1) {
                d += __shfl_xor_sync(0xffffffffu, d, o);
                s += __shfl_xor_sync(0xffffffffu, s, o);
            }
            if (lane == 0) { sdp[grp][wloc][n] = d; sss[grp][wloc][n] = s; }
        }
        __syncthreads();
        if (c < NNEG) {
            float d = sdp[grp][0][c] + sdp[grp][1][c] + sdp[grp][2][c] + sdp[grp][3][c];
            float s = sss[grp][0][c] + sss[grp][1][c] + sss[grp][2][c] + sss[grp][3][c];
            g_nlog[q * NNEG + c] = d / fmaxf(sqrtf(s), 1e-12f) * TAUI;
        }
    }
}

// ---------------------------------------------------------------------------
// Kernel 2: split-bf16 tensor GEMM + fused final.  grid=(4,32), block=256
//   All 128 blocks (1/SM, all resident): stage tiles, MMA, row max -> g_pmax,
//   counter arrive.  Blocks 0,1 wait, then softmax CE from g_pmax + g_nlog.
// ---------------------------------------------------------------------------
__global__ void __launch_bounds__(256, 1) k_mma(float* __restrict__ out) {
    extern __shared__ __align__(128) uint8_t smem[];
    __shared__ unsigned int s_tgt;
    __shared__ float sred[8];

    int t    = threadIdx.x;
    int lane = t & 31;
    int wid  = t >> 5;
    int flat  = blockIdx.y * 4 + blockIdx.x;
    int qbase = blockIdx.x * QTILE;
    int pbase = blockIdx.y * PTILE;

    // ---- stage 4 tiles (row-major, 272B stride) + rnorm ----
    {
        int row = t >> 1, half = t & 1;
        const uint4* sah = (const uint4*)((const char*)(g_qh + (size_t)(qbase + row) * CC) + half * 128);
        const uint4* sal = (const uint4*)((const char*)(g_ql + (size_t)(qbase + row) * CC) + half * 128);
        const uint4* sbh = (const uint4*)((const char*)(g_ph + (size_t)(pbase + row) * CC) + half * 128);
        const uint4* sbl = (const uint4*)((const char*)(g_pl + (size_t)(pbase + row) * CC) + half * 128);
        uint4* dah = (uint4*)(smem + AH_OFF + row * STRB + half * 128);
        uint4* dal = (uint4*)(smem + AL_OFF + row * STRB + half * 128);
        uint4* dbh = (uint4*)(smem + BH_OFF + row * STRB + half * 128);
        uint4* dbl = (uint4*)(smem + BL_OFF + row * STRB + half * 128);
        #pragma unroll
        for (int i = 0; i < 8; i++) {
            dah[i] = sah[i]; dal[i] = sal[i];
            dbh[i] = sbh[i]; dbl[i] = sbl[i];
        }
        if (t < 128) ((float*)(smem + RN_OFF))[t] = g_rnorm[pbase + t];
    }
    __syncthreads();

    uint32_t sb = smem_u32(smem);
    int m0 = wid * 16;
    uint32_t aoff = (uint32_t)((m0 + (lane & 15)) * STRB + ((lane & 16) ? 16 : 0));
    uint32_t boff = (uint32_t)(((lane & 7) + ((lane & 16) ? 8 : 0)) * STRB + ((lane & 8) ? 16 : 0));
    uint32_t aAh = sb + AH_OFF + aoff;
    uint32_t aAl = sb + AL_OFF + aoff;
    uint32_t bBh = sb + BH_OFF + boff;
    uint32_t bBl = sb + BL_OFF + boff;

    float acc[16][4];
    #pragma unroll
    for (int i = 0; i < 16; i++)
        #pragma unroll
        for (int j = 0; j < 4; j++) acc[i][j] = 0.0f;

    for (int ks = 0; ks < 8; ks++) {
        uint32_t kb = ks * 32;
        uint32_t ah0, ah1, ah2, ah3, al0, al1, al2, al3;
        LDSM4(ah0, ah1, ah2, ah3, aAh + kb);
        LDSM4(al0, al1, al2, al3, aAl + kb);
        #pragma unroll
        for (int j = 0; j < 8; j++) {
            uint32_t bh0, bh1, bh2, bh3, bl0, bl1, bl2, bl3;
            LDSM4(bh0, bh1, bh2, bh3, bBh + j * 16 * STRB + kb);
            LDSM4(bl0, bl1, bl2, bl3, bBl + j * 16 * STRB + kb);
            MMA16816(acc[2*j],   ah0, ah1, ah2, ah3, bh0, bh1);
            MMA16816(acc[2*j],   ah0, ah1, ah2, ah3, bl0, bl1);
            MMA16816(acc[2*j],   al0, al1, al2, al3, bh0, bh1);
            MMA16816(acc[2*j+1], ah0, ah1, ah2, ah3, bh2, bh3);
            MMA16816(acc[2*j+1], ah0, ah1, ah2, ah3, bl2, bl3);
            MMA16816(acc[2*j+1], al0, al1, al2, al3, bh2, bh3);
        }
    }

    // ---- sim = acc * rnorm, max over all 128 protos -> g_pmax ----
    {
        const float* rn = (const float*)(smem + RN_OFF);
        float mx1 = -3e38f, mx2 = -3e38f;
        #pragma unroll
        for (int nb = 0; nb < 16; nb++) {
            int n = nb * 8 + 2 * (lane & 3);
            float r0 = rn[n], r1 = rn[n + 1];
            mx1 = fmaxf(mx1, fmaxf(acc[nb][0] * r0, acc[nb][1] * r1));
            mx2 = fmaxf(mx2, fmaxf(acc[nb][2] * r0, acc[nb][3] * r1));
        }
        #pragma unroll
        for (int o = 1; o <= 2; o <<= 1) {
            mx1 = fmaxf(mx1, __shfl_xor_sync(0xffffffffu, mx1, o));
            mx2 = fmaxf(mx2, __shfl_xor_sync(0xffffffffu, mx2, o));
        }
        if ((lane & 3) == 0) {
            int q1 = qbase + m0 + (lane >> 2);
            g_pmax[q1 * NPT + blockIdx.y]       = mx1;
            g_pmax[(q1 + 8) * NPT + blockIdx.y] = mx2;
        }
    }

    // ---- publish + counter arrive; only blocks 0,1 wait ----
    __threadfence();
    __syncthreads();
    if (t == 0) {
        unsigned int old = atomicAdd(&g_cnt, 1u);
        s_tgt = ((old >> 7) << 7) + (unsigned int)NBLK;
    }
    __syncthreads();
    if (flat >= 2) return;
    if (t == 0) {
        while (*((volatile unsigned int*)&g_cnt) < s_tgt) { }
    }
    __syncthreads();
    __threadfence();   // acquire g_pmax (g_nlog already from prior kernel)

    // ---- final: thread-per-query softmax CE, block reduce, atomicAdd ----
    {
        int q = flat * 256 + t;
        float mx = -3e38f;
        #pragma unroll
        for (int j = 0; j < NPT; j++) mx = fmaxf(mx, g_pmax[q * NPT + j]);
        float l0 = mx * TAUI;

        float ln[NNEG];
        #pragma unroll
        for (int n = 0; n < NNEG; n++) ln[n] = g_nlog[q * NNEG + n];

        float m = l0;
        #pragma unroll
        for (int n = 0; n < NNEG; n++) m = fmaxf(m, ln[n]);
        float se = expf(l0 - m);
        #pragma unroll
        for (int n = 0; n < NNEG; n++) se += expf(ln[n] - m);
        float loss = logf(se) + m - l0;      // = -(log_softmax[0])

        #pragma unroll
        for (int o = 16; o; o >>= 1) loss += __shfl_xor_sync(0xffffffffu, loss, o);
        if (lane == 0) sred[wid] = loss;
        __syncthreads();
        if (t == 0) {
            float s = 0.0f;
            #pragma unroll
            for (int i = 0; i < 8; i++) s += sred[i];
            atomicAdd(out, s * (1.0f / (float)BK));
        }
    }
}

// ---------------------------------------------------------------------------
extern "C" void kernel_launch(void* const* d_in, const int* in_sizes, int n_in,
                              void* d_out, int out_size) {
    const float* qf   = (const float*)d_in[0];  // [8,128,512,512]
    const float* pool = (const float*)d_in[1];  // [4096,128]
    const float* neg  = (const float*)d_in[2];  // [8,64,7,128]
    const int*   qidx = (const int*)d_in[3];    // [8,64]
    float* out = (float*)d_out;

    cudaFuncSetAttribute(k_mma, cudaFuncAttributeMaxDynamicSharedMemorySize, SMEM_MMA);

    k_prep<<<768, 256>>>(pool, qf, qidx, neg, out);
    k_mma<<<dim3(BK / QTILE, PP / PTILE), 256, SMEM_MMA>>>(out);
}